// round 12
// baseline (speedup 1.0000x reference)
#include <cuda_runtime.h>
#include <cstdint>
#include <math.h>

#define NMAX 100000
#define EMAX 640000
#define D    128

// Scratch (all fp32 now; values are tf32-valid where noted)
__device__ float g_bufA[(size_t)NMAX * D];
__device__ float g_bufB[(size_t)NMAX * D];
__device__ float g_bufC[(size_t)NMAX * D];
__device__ float g_dinv[NMAX];
__device__ int   g_indeg[NMAX];
__device__ int   g_csr[NMAX + 1];
__device__ int   g_cursor[NMAX];
__device__ int   g_part[512];
__device__ int   g_srcS[EMAX];
__device__ float g_normS[EMAX];
__device__ int   g_idx64;
// Transposed tf32-rounded weights, n-major [n][k]
__device__ float g_WtIn[128 * 256];
__device__ float g_WtG [128 * 128];
__device__ float g_WtO1[128 * 128];

__device__ __forceinline__ float leaky(float v) { return v >= 0.f ? v : 0.01f * v; }
__device__ __forceinline__ float to_tf32(float v) {
    uint32_t u; asm("cvt.rna.tf32.f32 %0, %1;" : "=r"(u) : "f"(v));
    return __uint_as_float(u);
}

__device__ __forceinline__ void mma_tf32(float* c, const uint32_t* a, const uint32_t* b) {
    asm volatile(
        "mma.sync.aligned.m16n8k8.row.col.f32.tf32.tf32.f32 "
        "{%0,%1,%2,%3},{%4,%5,%6,%7},{%8,%9},{%0,%1,%2,%3};"
        : "+f"(c[0]), "+f"(c[1]), "+f"(c[2]), "+f"(c[3])
        : "r"(a[0]), "r"(a[1]), "r"(a[2]), "r"(a[3]), "r"(b[0]), "r"(b[1]));
}
__device__ __forceinline__ void ldsm4(uint32_t* r, uint32_t addr) {
    asm volatile("ldmatrix.sync.aligned.m8n8.x4.shared.b16 {%0,%1,%2,%3}, [%4];"
                 : "=r"(r[0]), "=r"(r[1]), "=r"(r[2]), "=r"(r[3]) : "r"(addr));
}

// ---------------------------------------------------------------------------
// TF32 GEMM: C = A[M,K] @ W[K,128] (W given transposed n-major, tf32-valid).
// 128x128 tile, 8 warps (2x4), reg-prefetch, K staged 32 at a time.
// mode 0: C0 = acc (raw fp32)
// mode 1: C0 = tf32(leaky(acc + bias))
// mode 3: out[row*2+c] = sum_col leaky(acc+bias)*w2[col][c] + b2[c]
// ---------------------------------------------------------------------------
#define RSF 36  // smem row stride in floats (144B)

struct Frag { float av[16], bv[16]; };

__device__ __forceinline__ void prefetch(
    Frag& f, const float* __restrict__ A, const float* __restrict__ Wt,
    int rowBase, int M, int K, int lda, int ldw, int k0, int tid, int cvtA)
{
    const int row = tid >> 1;
    const int kOff = (tid & 1) * 16;
    const int grow = rowBase + row;
    if (lda & 3) {  // scalar path (G1: lda=239, needs cvt)
#pragma unroll
        for (int j = 0; j < 16; j++) {
            int gk = k0 + kOff + j;
            float v = (grow < M && gk < K) ? A[(size_t)grow * lda + gk] : 0.f;
            f.av[j] = cvtA ? to_tf32(v) : v;
        }
    } else {        // vector path: K multiple of 32, data already tf32-valid
#pragma unroll
        for (int j = 0; j < 4; j++) {
            float4 v = make_float4(0.f, 0.f, 0.f, 0.f);
            if (grow < M)
                v = *(const float4*)(A + (size_t)grow * lda + k0 + kOff + 4 * j);
            *(float4*)&f.av[4 * j] = v;
        }
    }
#pragma unroll
    for (int j = 0; j < 4; j++)
        *(float4*)&f.bv[4 * j] = *(const float4*)(Wt + (size_t)row * ldw + k0 + kOff + 4 * j);
}

__global__ __launch_bounds__(256, 2) void k_gemm(
    const float* __restrict__ A, const float* __restrict__ Wt,
    const float* __restrict__ bias,
    float* __restrict__ C0,
    const float* __restrict__ w2, const float* __restrict__ b2,
    float* __restrict__ outp,
    int M, int K, int Kpad, int lda, int ldw, int mode)
{
    __shared__ float sBias[128];
    __shared__ float sW2[256];
    __shared__ float sProj[128][2];
    __shared__ __align__(16) float As[128 * RSF];
    __shared__ __align__(16) float Bs[128 * RSF];

    const int tid  = threadIdx.x;
    const int wid  = tid >> 5;
    const int lane = tid & 31;
    const int g    = lane >> 2;
    const int tig  = lane & 3;
    const int wm   = (wid >> 2) * 64;
    const int wn   = (wid & 3) * 32;
    const int rowBase = blockIdx.x * 128;

    if (mode != 0 && tid < 128) sBias[tid] = bias[tid];
    if (mode == 3) {
        sW2[tid] = w2[tid];
        if (tid < 128) { sProj[tid][0] = 0.f; sProj[tid][1] = 0.f; }
    }

    // ldmatrix lane addresses
    const uint32_t aB = (uint32_t)__cvta_generic_to_shared(As);
    const uint32_t bB = (uint32_t)__cvta_generic_to_shared(Bs);
    const int aRow = ((lane >> 3) & 1) * 8 + (lane & 7);
    const int aC   = (lane >> 4) * 16;   // byte offset (k-chunk)
    uint32_t aAddr[4];
#pragma unroll
    for (int mt = 0; mt < 4; mt++)
        aAddr[mt] = aB + (uint32_t)(((wm + mt * 16 + aRow) * RSF) * 4 + aC);
    const int bT = lane >> 3;
    const int bN = ((bT >> 1) & 1) * 8 + (lane & 7);
    const int bC = (bT & 1) * 16;
    uint32_t bAddr[2];
#pragma unroll
    for (int p = 0; p < 2; p++)
        bAddr[p] = bB + (uint32_t)(((wn + p * 16 + bN) * RSF) * 4 + bC);

    float acc[4][4][4];
#pragma unroll
    for (int mt = 0; mt < 4; mt++)
#pragma unroll
        for (int nt = 0; nt < 4; nt++)
#pragma unroll
            for (int j = 0; j < 4; j++) acc[mt][nt][j] = 0.f;

    const int nStages = Kpad >> 5;
    Frag f;
    prefetch(f, A, Wt, rowBase, M, K, lda, ldw, 0, tid, 1);

    const int sRow = tid >> 1, sOff = (tid & 1) * 16;
    for (int st = 0; st < nStages; st++) {
        {
            float* ap = As + sRow * RSF + sOff;
            float* bp = Bs + sRow * RSF + sOff;
#pragma unroll
            for (int j = 0; j < 4; j++) {
                *(float4*)(ap + 4 * j) = *(float4*)&f.av[4 * j];
                *(float4*)(bp + 4 * j) = *(float4*)&f.bv[4 * j];
            }
        }
        __syncthreads();

        if (st + 1 < nStages)
            prefetch(f, A, Wt, rowBase, M, K, lda, ldw, (st + 1) << 5, tid, 1);

#pragma unroll
        for (int j = 0; j < 4; j++) {      // 4 k8-steps, byte offset 32j
            uint32_t bfr[2][4];
            ldsm4(bfr[0], bAddr[0] + 32 * j);
            ldsm4(bfr[1], bAddr[1] + 32 * j);
#pragma unroll
            for (int mt = 0; mt < 4; mt++) {
                uint32_t afr[4];
                ldsm4(afr, aAddr[mt] + 32 * j);
#pragma unroll
                for (int nt = 0; nt < 4; nt++)
                    mma_tf32(acc[mt][nt], afr, &bfr[nt >> 1][(nt & 1) * 2]);
            }
        }
        __syncthreads();
    }

    // ---- epilogue ----
    if (mode == 3) {
#pragma unroll
        for (int mt = 0; mt < 4; mt++) {
            float p00 = 0.f, p01 = 0.f, p10 = 0.f, p11 = 0.f;
#pragma unroll
            for (int nt = 0; nt < 4; nt++) {
                int cn = wn + nt * 8 + 2 * tig;
                float b0 = sBias[cn], b1 = sBias[cn + 1];
                float w00 = sW2[cn * 2], w01 = sW2[cn * 2 + 1];
                float w10 = sW2[cn * 2 + 2], w11 = sW2[cn * 2 + 3];
                float* c = acc[mt][nt];
                float h0 = leaky(c[0] + b0), h1 = leaky(c[1] + b1);
                p00 += h0 * w00 + h1 * w10;
                p01 += h0 * w01 + h1 * w11;
                float h2 = leaky(c[2] + b0), h3 = leaky(c[3] + b1);
                p10 += h2 * w00 + h3 * w10;
                p11 += h2 * w01 + h3 * w11;
            }
#pragma unroll
            for (int off = 1; off < 4; off <<= 1) {
                p00 += __shfl_xor_sync(0xFFFFFFFFu, p00, off);
                p01 += __shfl_xor_sync(0xFFFFFFFFu, p01, off);
                p10 += __shfl_xor_sync(0xFFFFFFFFu, p10, off);
                p11 += __shfl_xor_sync(0xFFFFFFFFu, p11, off);
            }
            if (tig == 0) {
                int lr = wm + mt * 16 + g;
                atomicAdd(&sProj[lr][0], p00);
                atomicAdd(&sProj[lr][1], p01);
                atomicAdd(&sProj[lr + 8][0], p10);
                atomicAdd(&sProj[lr + 8][1], p11);
            }
        }
        __syncthreads();
        {
            int lr = tid >> 1, c = tid & 1;
            int grow = rowBase + lr;
            if (grow < M) outp[(size_t)grow * 2 + c] = sProj[lr][c] + b2[c];
        }
        return;
    }

#pragma unroll
    for (int mt = 0; mt < 4; mt++) {
        int r0 = rowBase + wm + mt * 16 + g;
        int r1 = r0 + 8;
        bool v0 = r0 < M, v1 = r1 < M;
#pragma unroll
        for (int nt = 0; nt < 4; nt++) {
            int cn = wn + nt * 8 + 2 * tig;
            float* c = acc[mt][nt];
            if (mode == 1) {
                float b0 = sBias[cn], b1 = sBias[cn + 1];
                if (v0) {
                    float2 o = { to_tf32(leaky(c[0] + b0)), to_tf32(leaky(c[1] + b1)) };
                    *(float2*)(C0 + (size_t)r0 * D + cn) = o;
                }
                if (v1) {
                    float2 o = { to_tf32(leaky(c[2] + b0)), to_tf32(leaky(c[3] + b1)) };
                    *(float2*)(C0 + (size_t)r1 * D + cn) = o;
                }
            } else {
                if (v0) { float2 o = { c[0], c[1] }; *(float2*)(C0 + (size_t)r0 * D + cn) = o; }
                if (v1) { float2 o = { c[2], c[3] }; *(float2*)(C0 + (size_t)r1 * D + cn) = o; }
            }
        }
    }
}

// ---------------------------------------------------------------------------
// Weight prep: transpose to n-major + tf32 round.  W_in padded to 256 K-rows.
// ---------------------------------------------------------------------------
__global__ void k_prepW(const float* __restrict__ Win, const float* __restrict__ Wg,
                        const float* __restrict__ Wo1, int Kin)
{
    int i = blockIdx.x * blockDim.x + threadIdx.x;
    if (i < 128 * 256) {
        int n = i >> 8, k = i & 255;
        g_WtIn[n * 256 + k] = to_tf32(k < Kin ? Win[(size_t)k * D + n] : 0.f);
    } else if (i < 128 * 256 + 128 * 128) {
        int j = i - 128 * 256;
        int n = j >> 7, k = j & 127;
        g_WtG[n * 128 + k] = to_tf32(Wg[(size_t)k * D + n]);
    } else if (i < 128 * 256 + 2 * 128 * 128) {
        int j = i - 128 * 256 - 128 * 128;
        int n = j >> 7, k = j & 127;
        g_WtO1[n * 128 + k] = to_tf32(Wo1[(size_t)k * D + n]);
    }
}

// ---------------------------------------------------------------------------
// Edge dtype detection + CSR build
// ---------------------------------------------------------------------------
__global__ void k_detect(const void* __restrict__ ei) {
    const long long* p = (const long long*)ei;
    int ok = 1;
    for (int i = 0; i < 16; i++) {
        long long v = p[i];
        if (v < 0 || v >= NMAX) ok = 0;
    }
    g_idx64 = ok;
}
__device__ __forceinline__ int edge_at(const void* ei, long long idx) {
    if (g_idx64) return (int)((const long long*)ei)[idx];
    return ((const int*)ei)[idx];
}

__global__ void k_zero(int* indeg, int n) {
    int i = blockIdx.x * blockDim.x + threadIdx.x;
    if (i < n) indeg[i] = 0;
}
__global__ void k_count(const void* __restrict__ ei, int* indeg, int e) {
    int i = blockIdx.x * blockDim.x + threadIdx.x;
    if (i < e) atomicAdd(&indeg[edge_at(ei, (long long)e + i)], 1);
}
__global__ void k_dinv(const int* __restrict__ indeg, float* dinv, int n) {
    int i = blockIdx.x * blockDim.x + threadIdx.x;
    if (i < n) dinv[i] = rsqrtf(1.0f + (float)indeg[i]);
}

__global__ void k_scan1(const int* __restrict__ indeg, int* __restrict__ csr,
                        int* __restrict__ part, int n)
{
    __shared__ int sh[256];
    int t = threadIdx.x;
    int i = blockIdx.x * 256 + t;
    int v = (i < n) ? indeg[i] : 0;
    sh[t] = v;
    __syncthreads();
#pragma unroll
    for (int off = 1; off < 256; off <<= 1) {
        int x = (t >= off) ? sh[t - off] : 0;
        __syncthreads();
        sh[t] += x;
        __syncthreads();
    }
    if (i < n) csr[i] = sh[t] - v;
    if (t == 255) part[blockIdx.x] = sh[t];
}

__global__ void k_scan2(int* __restrict__ part, int nb) {
    __shared__ int sh[512];
    int t = threadIdx.x;
    int v = (t < nb) ? part[t] : 0;
    sh[t] = v;
    __syncthreads();
#pragma unroll
    for (int off = 1; off < 512; off <<= 1) {
        int x = (t >= off) ? sh[t - off] : 0;
        __syncthreads();
        sh[t] += x;
        __syncthreads();
    }
    if (t < nb) part[t] = sh[t] - v;
}

__global__ void k_scan3(int* __restrict__ csr, const int* __restrict__ part,
                        const int* __restrict__ indeg, int* __restrict__ cursor, int n)
{
    int i = blockIdx.x * blockDim.x + threadIdx.x;
    if (i >= n) return;
    int base = csr[i] + part[i >> 8];
    csr[i] = base;
    cursor[i] = 0;
    if (i == n - 1) csr[n] = base + indeg[i];
}

__global__ void k_fill(const void* __restrict__ ei, const float* __restrict__ dinv,
                       const int* __restrict__ csr, int* __restrict__ cursor,
                       int* __restrict__ srcS, float* __restrict__ normS, int E)
{
    int i = blockIdx.x * blockDim.x + threadIdx.x;
    if (i >= E) return;
    int s = edge_at(ei, i);
    int d = edge_at(ei, (long long)E + i);
    int p = csr[d] + atomicAdd(&cursor[d], 1);
    srcS[p] = s;
    normS[p] = dinv[s] * dinv[d];
}

// ---------------------------------------------------------------------------
// Gather aggregation: one warp per dst node; fp32 in, tf32-valid fp32 out.
// ---------------------------------------------------------------------------
__global__ __launch_bounds__(256) void k_gather(
    const float* __restrict__ t, const int* __restrict__ csr,
    const int* __restrict__ srcS, const float* __restrict__ normS,
    const float* __restrict__ dinv, const float* __restrict__ bias,
    float* __restrict__ agg, int N)
{
    int warp = (blockIdx.x * blockDim.x + threadIdx.x) >> 5;
    int lane = threadIdx.x & 31;
    if (warp >= N) return;
    int beg = csr[warp], end = csr[warp + 1];
    float dv = dinv[warp];
    float dv2 = dv * dv;
    float4 b4 = *(const float4*)(bias + lane * 4);
    float4 a  = *(const float4*)(t + (size_t)warp * D + lane * 4);
    float4 acc;
    acc.x = a.x * dv2 + b4.x;
    acc.y = a.y * dv2 + b4.y;
    acc.z = a.z * dv2 + b4.z;
    acc.w = a.w * dv2 + b4.w;
    for (int e = beg; e < end; e++) {
        int s = srcS[e];
        float nm = normS[e];
        float4 v = *(const float4*)(t + (size_t)s * D + lane * 4);
        acc.x += nm * v.x;
        acc.y += nm * v.y;
        acc.z += nm * v.z;
        acc.w += nm * v.w;
    }
    float4 o;
    o.x = to_tf32(acc.x);
    o.y = to_tf32(acc.y);
    o.z = to_tf32(acc.z);
    o.w = to_tf32(acc.w);
    *(float4*)(agg + (size_t)warp * D + lane * 4) = o;
}

// ---------------------------------------------------------------------------
// Host launcher
// ---------------------------------------------------------------------------
extern "C" void kernel_launch(void* const* d_in, const int* in_sizes, int n_in,
                              void* d_out, int out_size)
{
    const float* x    = (const float*)d_in[0];
    const void*  ei   = d_in[1];
    const float* W_in = (const float*)d_in[3];
    const float* b_in = (const float*)d_in[4];
    const float* W_g  = (const float*)d_in[5];
    const float* b_g  = (const float*)d_in[6];
    const float* W_o1 = (const float*)d_in[7];
    const float* b_o1 = (const float*)d_in[8];
    const float* W_o2 = (const float*)d_in[9];
    const float* b_o2 = (const float*)d_in[10];
    float*       out  = (float*)d_out;

    const int ND = 239;
    const int N  = in_sizes[0] / ND;
    const int E  = in_sizes[1] / 2;

    float *bufA, *bufB, *bufC, *dinv, *normS, *WtIn, *WtG, *WtO1;
    int *indeg, *csr, *cursor, *part, *srcS;
    cudaGetSymbolAddress((void**)&bufA,  g_bufA);
    cudaGetSymbolAddress((void**)&bufB,  g_bufB);
    cudaGetSymbolAddress((void**)&bufC,  g_bufC);
    cudaGetSymbolAddress((void**)&dinv,  g_dinv);
    cudaGetSymbolAddress((void**)&indeg, g_indeg);
    cudaGetSymbolAddress((void**)&csr,   g_csr);
    cudaGetSymbolAddress((void**)&cursor,g_cursor);
    cudaGetSymbolAddress((void**)&part,  g_part);
    cudaGetSymbolAddress((void**)&srcS,  g_srcS);
    cudaGetSymbolAddress((void**)&normS, g_normS);
    cudaGetSymbolAddress((void**)&WtIn,  g_WtIn);
    cudaGetSymbolAddress((void**)&WtG,   g_WtG);
    cudaGetSymbolAddress((void**)&WtO1,  g_WtO1);

    const int TB = 256;
    const int nBlk = (N + 255) / 256;

    k_detect<<<1, 1>>>(ei);
    k_zero<<<nBlk, TB>>>(indeg, N);
    k_count<<<(E + TB - 1) / TB, TB>>>(ei, indeg, E);
    k_dinv<<<nBlk, TB>>>(indeg, dinv, N);
    k_scan1<<<nBlk, TB>>>(indeg, csr, part, N);
    k_scan2<<<1, 512>>>(part, nBlk);
    k_scan3<<<nBlk, TB>>>(csr, part, indeg, cursor, N);
    k_fill<<<(E + TB - 1) / TB, TB>>>(ei, dinv, csr, cursor, srcS, normS, E);
    k_prepW<<<(128 * 256 + 2 * 128 * 128 + TB - 1) / TB, TB>>>(W_in, W_g, W_o1, ND);

    const int grid = (N + 127) / 128;
    const int gGrid = ((size_t)N * 32 + TB - 1) / TB;
    // G1: h0 = tf32(leaky(x @ W_in + b_in)) -> A
    k_gemm<<<grid, TB>>>(x, WtIn, b_in, bufA, nullptr, nullptr, nullptr,
                         N, ND, 256, ND, 256, 1);
    // G2: t1 = h0 @ W_g -> B (fp32)
    k_gemm<<<grid, TB>>>(bufA, WtG, nullptr, bufB, nullptr, nullptr, nullptr,
                         N, 128, 128, 128, 128, 0);
    k_gather<<<gGrid, TB>>>(bufB, csr, srcS, normS, dinv, b_g, bufC, N);
    // G3: t2 = h1 @ W_g -> B (fp32)
    k_gemm<<<grid, TB>>>(bufC, WtG, nullptr, bufB, nullptr, nullptr, nullptr,
                         N, 128, 128, 128, 128, 0);
    k_gather<<<gGrid, TB>>>(bufB, csr, srcS, normS, dinv, b_g, bufA, N);
    // G4: out = leaky(h2 @ W_o1 + b_o1) @ W_o2 + b_o2  (fully fused)
    k_gemm<<<grid, TB>>>(bufA, WtO1, b_o1, nullptr, W_o2, b_o2, out,
                         N, 128, 128, 128, 128, 3);
}

// round 13
// speedup vs baseline: 1.0790x; 1.0790x over previous
#include <cuda_runtime.h>
#include <cuda_bf16.h>
#include <cstdint>
#include <math.h>

#define NMAX 100000
#define EMAX 640000
#define D    128

// Scratch. bufA/C packed-split activations (uint32), bufB fp32 t.
__device__ uint32_t g_bufA[(size_t)NMAX * D];
__device__ float    g_bufB[(size_t)NMAX * D];
__device__ uint32_t g_bufC[(size_t)NMAX * D];
__device__ float    g_dinv[NMAX];
__device__ int      g_indeg[NMAX];
__device__ int      g_csr[NMAX + 1];
__device__ int      g_cursor[NMAX];
__device__ int      g_part[512];
__device__ int      g_srcS[EMAX];
__device__ float    g_normS[EMAX];
__device__ int      g_idx64;
// Pre-split weights (packed hi|lo<<16).
__device__ uint32_t g_WinPk[256 * D];   // k-major [k][n], K padded 256 (G1)
__device__ uint32_t g_WgT [D * D];      // n-major [n][k] (G2/G3)
__device__ uint32_t g_Wo1T[D * D];      // n-major [n][k] (G4)

__device__ __forceinline__ float leaky(float v) { return v >= 0.f ? v : 0.01f * v; }

__device__ __forceinline__ uint32_t packsplit(float v) {
    __nv_bfloat16 h = __float2bfloat16(v);
    __nv_bfloat16 l = __float2bfloat16(v - __bfloat162float(h));
    return (uint32_t)__bfloat16_as_ushort(h) | ((uint32_t)__bfloat16_as_ushort(l) << 16);
}
__device__ __forceinline__ uint32_t pack_hi(float a0, float a1) {
    __nv_bfloat16 h0 = __float2bfloat16(a0), h1 = __float2bfloat16(a1);
    return (uint32_t)__bfloat16_as_ushort(h0) | ((uint32_t)__bfloat16_as_ushort(h1) << 16);
}
__device__ __forceinline__ uint32_t pack_lo(float a0, float a1) {
    __nv_bfloat16 h0 = __float2bfloat16(a0), h1 = __float2bfloat16(a1);
    __nv_bfloat16 l0 = __float2bfloat16(a0 - __bfloat162float(h0));
    __nv_bfloat16 l1 = __float2bfloat16(a1 - __bfloat162float(h1));
    return (uint32_t)__bfloat16_as_ushort(l0) | ((uint32_t)__bfloat16_as_ushort(l1) << 16);
}

__device__ __forceinline__ void mma16816(float* c, const uint32_t* a, const uint32_t* b) {
    asm volatile(
        "mma.sync.aligned.m16n8k16.row.col.f32.bf16.bf16.f32 "
        "{%0,%1,%2,%3}, {%4,%5,%6,%7}, {%8,%9}, {%0,%1,%2,%3};"
        : "+f"(c[0]), "+f"(c[1]), "+f"(c[2]), "+f"(c[3])
        : "r"(a[0]), "r"(a[1]), "r"(a[2]), "r"(a[3]), "r"(b[0]), "r"(b[1]));
}
__device__ __forceinline__ void ldsm4(uint32_t* r, uint32_t addr) {
    asm volatile("ldmatrix.sync.aligned.m8n8.x4.shared.b16 {%0,%1,%2,%3}, [%4];"
                 : "=r"(r[0]), "=r"(r[1]), "=r"(r[2]), "=r"(r[3]) : "r"(addr));
}

#define RSA 40   // A smem row stride (halves); 5x16B odd -> conflict-free
#define RSB 136  // B resident row stride (halves); 17x16B odd -> conflict-free

// Dynamic smem layout for fast kernel (bytes)
#define OFF_BH   0
#define OFF_BL   (OFF_BH + 128 * RSB * 2)      // 34816
#define OFF_AH   (OFF_BL + 128 * RSB * 2)      // 69632
#define OFF_AL   (OFF_AH + 128 * RSA * 2)      // 79872
#define OFF_BIAS (OFF_AL + 128 * RSA * 2)      // 90112
#define OFF_W2   (OFF_BIAS + 512)              // 90624
#define OFF_PROJ (OFF_W2 + 1024)               // 91648
#define SMEM_FAST (OFF_PROJ + 1024)            // 92672

// ---------------------------------------------------------------------------
// FAST GEMM (K=128): A packed-split uint32, W resident n-major packed.
// mode 0: C0f = acc (fp32).  mode 3: fused leaky+bias+projection -> outp.
// ---------------------------------------------------------------------------
__global__ __launch_bounds__(256, 2) void k_gemm_fast(
    const uint32_t* __restrict__ A, const uint32_t* __restrict__ Wt,
    const float* __restrict__ bias,
    float* __restrict__ C0f,
    const float* __restrict__ w2, const float* __restrict__ b2,
    float* __restrict__ outp,
    int M, int mode)
{
    extern __shared__ __align__(16) char sm[];
    __nv_bfloat16* BsHi = (__nv_bfloat16*)(sm + OFF_BH);
    __nv_bfloat16* BsLo = (__nv_bfloat16*)(sm + OFF_BL);
    __nv_bfloat16* AsHi = (__nv_bfloat16*)(sm + OFF_AH);
    __nv_bfloat16* AsLo = (__nv_bfloat16*)(sm + OFF_AL);
    float* sBias = (float*)(sm + OFF_BIAS);
    float* sW2   = (float*)(sm + OFF_W2);
    float* sProj = (float*)(sm + OFF_PROJ);

    const int tid  = threadIdx.x;
    const int wid  = tid >> 5;
    const int lane = tid & 31;
    const int g    = lane >> 2;
    const int tig  = lane & 3;
    const int wm   = (wid >> 2) * 64;
    const int wn   = (wid & 3) * 32;
    const int rowBase = blockIdx.x * 128;

    if (mode == 3) {
        if (tid < 128) sBias[tid] = bias[tid];
        sW2[tid] = w2[tid];
        if (tid < 128) { sProj[tid * 2] = 0.f; sProj[tid * 2 + 1] = 0.f; }
    }

    // ---- load resident B (whole 128x128 weight, n-major packed) ----
    {
        int n = tid >> 1;
        int kb = (tid & 1) * 64;
        const uint32_t* wrow = Wt + (size_t)n * 128 + kb;
#pragma unroll
        for (int i = 0; i < 32; i++) {
            uint2 q = *(const uint2*)(wrow + 2 * i);
            *(uint32_t*)(BsHi + n * RSB + kb + 2 * i) = __byte_perm(q.x, q.y, 0x5410);
            *(uint32_t*)(BsLo + n * RSB + kb + 2 * i) = __byte_perm(q.x, q.y, 0x7632);
        }
    }

    // ldmatrix lane addresses
    const uint32_t aBH = (uint32_t)__cvta_generic_to_shared(AsHi);
    const uint32_t aBL = (uint32_t)__cvta_generic_to_shared(AsLo);
    const uint32_t bBH = (uint32_t)__cvta_generic_to_shared(BsHi);
    const uint32_t bBL = (uint32_t)__cvta_generic_to_shared(BsLo);
    const int aRow  = wm + (lane & 15);
    const int aColH = (lane >> 4) * 8;
    uint32_t aOff[4];
#pragma unroll
    for (int mt = 0; mt < 4; mt++)
        aOff[mt] = (uint32_t)(((aRow + mt * 16) * RSA + aColH) * 2);
    const int bQ  = lane >> 3, bL7 = lane & 7;
    const int bNo = ((bQ >> 1) & 1) * 8 + bL7;
    const int bKo = (bQ & 1) * 8;
    uint32_t bOff[2];
#pragma unroll
    for (int p = 0; p < 2; p++)
        bOff[p] = (uint32_t)(((wn + p * 16 + bNo) * RSB + bKo) * 2);

    float acc[4][4][4];
#pragma unroll
    for (int mt = 0; mt < 4; mt++)
#pragma unroll
        for (int nt = 0; nt < 4; nt++)
#pragma unroll
            for (int j = 0; j < 4; j++) acc[mt][nt][j] = 0.f;

    // A register prefetch (stage 0)
    uint32_t aHi[8], aLo[8];
#pragma unroll
    for (int i = 0; i < 8; i++) {
        int w = tid + i * 256;
        int row = w >> 4, kw = w & 15;
        int grow = rowBase + row;
        uint2 p = make_uint2(0u, 0u);
        if (grow < M) p = *(const uint2*)(A + (size_t)grow * 128 + kw * 2);
        aHi[i] = __byte_perm(p.x, p.y, 0x5410);
        aLo[i] = __byte_perm(p.x, p.y, 0x7632);
    }

    for (int st = 0; st < 4; st++) {
#pragma unroll
        for (int i = 0; i < 8; i++) {
            int w = tid + i * 256;
            int row = w >> 4, kw = w & 15;
            int so = row * RSA + kw * 2;
            *(uint32_t*)(AsHi + so) = aHi[i];
            *(uint32_t*)(AsLo + so) = aLo[i];
        }
        __syncthreads();

        if (st < 3) {
            int k0 = (st + 1) << 5;
#pragma unroll
            for (int i = 0; i < 8; i++) {
                int w = tid + i * 256;
                int row = w >> 4, kw = w & 15;
                int grow = rowBase + row;
                uint2 p = make_uint2(0u, 0u);
                if (grow < M) p = *(const uint2*)(A + (size_t)grow * 128 + k0 + kw * 2);
                aHi[i] = __byte_perm(p.x, p.y, 0x5410);
                aLo[i] = __byte_perm(p.x, p.y, 0x7632);
            }
        }

        const int stB = st * 64;  // stage byte offset in B k-dimension
#pragma unroll
        for (int kkB = 0; kkB < 64; kkB += 32) {
            uint32_t bh[2][4], bl[2][4];
            ldsm4(bh[0], bBH + bOff[0] + stB + kkB);
            ldsm4(bh[1], bBH + bOff[1] + stB + kkB);
            ldsm4(bl[0], bBL + bOff[0] + stB + kkB);
            ldsm4(bl[1], bBL + bOff[1] + stB + kkB);
#pragma unroll
            for (int mt = 0; mt < 4; mt++) {
                uint32_t ah[4], al[4];
                ldsm4(ah, aBH + aOff[mt] + kkB);
                ldsm4(al, aBL + aOff[mt] + kkB);
#pragma unroll
                for (int nt = 0; nt < 4; nt++) {
                    const uint32_t* bhp = &bh[nt >> 1][(nt & 1) * 2];
                    const uint32_t* blp = &bl[nt >> 1][(nt & 1) * 2];
                    mma16816(acc[mt][nt], ah, bhp);
                    mma16816(acc[mt][nt], ah, blp);
                    mma16816(acc[mt][nt], al, bhp);
                }
            }
        }
        __syncthreads();
    }

    if (mode == 3) {
#pragma unroll
        for (int mt = 0; mt < 4; mt++) {
            float p00 = 0.f, p01 = 0.f, p10 = 0.f, p11 = 0.f;
#pragma unroll
            for (int nt = 0; nt < 4; nt++) {
                int cn = wn + nt * 8 + 2 * tig;
                float b0 = sBias[cn], b1 = sBias[cn + 1];
                float w00 = sW2[cn * 2], w01 = sW2[cn * 2 + 1];
                float w10 = sW2[cn * 2 + 2], w11 = sW2[cn * 2 + 3];
                float* c = acc[mt][nt];
                float h0 = leaky(c[0] + b0), h1 = leaky(c[1] + b1);
                p00 += h0 * w00 + h1 * w10;
                p01 += h0 * w01 + h1 * w11;
                float h2 = leaky(c[2] + b0), h3 = leaky(c[3] + b1);
                p10 += h2 * w00 + h3 * w10;
                p11 += h2 * w01 + h3 * w11;
            }
#pragma unroll
            for (int off = 1; off < 4; off <<= 1) {
                p00 += __shfl_xor_sync(0xFFFFFFFFu, p00, off);
                p01 += __shfl_xor_sync(0xFFFFFFFFu, p01, off);
                p10 += __shfl_xor_sync(0xFFFFFFFFu, p10, off);
                p11 += __shfl_xor_sync(0xFFFFFFFFu, p11, off);
            }
            if (tig == 0) {
                int lr = wm + mt * 16 + g;
                atomicAdd(&sProj[lr * 2], p00);
                atomicAdd(&sProj[lr * 2 + 1], p01);
                atomicAdd(&sProj[(lr + 8) * 2], p10);
                atomicAdd(&sProj[(lr + 8) * 2 + 1], p11);
            }
        }
        __syncthreads();
        {
            int lr = tid >> 1, c = tid & 1;
            int grow = rowBase + lr;
            if (grow < M) outp[(size_t)grow * 2 + c] = sProj[lr * 2 + c] + b2[c];
        }
        return;
    }

#pragma unroll
    for (int mt = 0; mt < 4; mt++) {
        int r0 = rowBase + wm + mt * 16 + g;
        int r1 = r0 + 8;
        bool v0 = r0 < M, v1 = r1 < M;
#pragma unroll
        for (int nt = 0; nt < 4; nt++) {
            int cn = wn + nt * 8 + 2 * tig;
            float* c = acc[mt][nt];
            if (v0) { float2 o = { c[0], c[1] }; *(float2*)(C0f + (size_t)r0 * D + cn) = o; }
            if (v1) { float2 o = { c[2], c[3] }; *(float2*)(C0f + (size_t)r1 * D + cn) = o; }
        }
    }
}

// ---------------------------------------------------------------------------
// G1 GEMM (K=239, fp32 A, k-major packed W, per-stage staging) — R11 path.
// Output: packed-split leaky(acc + bias).
// ---------------------------------------------------------------------------
struct FragG1 { uint32_t aHi[8], aLo[8], bHi[8], bLo[8]; };

__device__ __forceinline__ void prefetchG1(
    FragG1& f, const float* __restrict__ A, const uint32_t* __restrict__ Wpk,
    int rowBase, int M, int K, int lda, int k0, int tid)
{
#pragma unroll
    for (int i = 0; i < 8; i++) {
        int w = tid + i * 256;
        int row = w >> 4, kw = w & 15;
        int grow = rowBase + row, gk = k0 + kw * 2;
        float a0 = 0.f, a1 = 0.f;
        if (grow < M) {
            const float* ap = A + (size_t)grow * lda;
            if (gk < K)     a0 = ap[gk];
            if (gk + 1 < K) a1 = ap[gk + 1];
        }
        f.aHi[i] = pack_hi(a0, a1);
        f.aLo[i] = pack_lo(a0, a1);
    }
#pragma unroll
    for (int i = 0; i < 8; i++) {
        int w = tid + i * 256;
        int n = w & 127, kw = w >> 7;
        int gk = k0 + kw * 2;
        uint32_t q0 = Wpk[(size_t)gk * D + n];
        uint32_t q1 = Wpk[(size_t)(gk + 1) * D + n];
        f.bHi[i] = __byte_perm(q0, q1, 0x5410);
        f.bLo[i] = __byte_perm(q0, q1, 0x7632);
    }
}

__global__ __launch_bounds__(256, 2) void k_gemm_g1(
    const float* __restrict__ A, const uint32_t* __restrict__ Wpk,
    const float* __restrict__ bias, uint32_t* __restrict__ C0p,
    int M, int K, int lda)
{
    __shared__ float sBias[128];
    __shared__ __align__(16) __nv_bfloat16 AsHi[128 * RSA];
    __shared__ __align__(16) __nv_bfloat16 AsLo[128 * RSA];
    __shared__ __align__(16) __nv_bfloat16 BsHi[128 * RSA];
    __shared__ __align__(16) __nv_bfloat16 BsLo[128 * RSA];

    const int tid  = threadIdx.x;
    const int wid  = tid >> 5;
    const int lane = tid & 31;
    const int g    = lane >> 2;
    const int tig  = lane & 3;
    const int wm   = (wid >> 2) * 64;
    const int wn   = (wid & 3) * 32;
    const int rowBase = blockIdx.x * 128;

    if (tid < 128) sBias[tid] = bias[tid];

    const uint32_t aBH = (uint32_t)__cvta_generic_to_shared(AsHi);
    const uint32_t aBL = (uint32_t)__cvta_generic_to_shared(AsLo);
    const uint32_t bBH = (uint32_t)__cvta_generic_to_shared(BsHi);
    const uint32_t bBL = (uint32_t)__cvta_generic_to_shared(BsLo);
    const int aRow  = wm + (lane & 15);
    const int aColH = (lane >> 4) * 8;
    uint32_t aOff[4];
#pragma unroll
    for (int mt = 0; mt < 4; mt++)
        aOff[mt] = (uint32_t)(((aRow + mt * 16) * RSA + aColH) * 2);
    const int bQ  = lane >> 3, bL7 = lane & 7;
    const int bNo = ((bQ >> 1) & 1) * 8 + bL7;
    const int bKo = (bQ & 1) * 8;
    uint32_t bOff[2];
#pragma unroll
    for (int p = 0; p < 2; p++)
        bOff[p] = (uint32_t)(((wn + p * 16 + bNo) * RSA + bKo) * 2);

    float acc[4][4][4];
#pragma unroll
    for (int mt = 0; mt < 4; mt++)
#pragma unroll
        for (int nt = 0; nt < 4; nt++)
#pragma unroll
            for (int j = 0; j < 4; j++) acc[mt][nt][j] = 0.f;

    const int nStages = (K + 31) >> 5;
    FragG1 f;
    prefetchG1(f, A, Wpk, rowBase, M, K, lda, 0, tid);

    for (int st = 0; st < nStages; st++) {
#pragma unroll
        for (int i = 0; i < 8; i++) {
            int w = tid + i * 256;
            int row = w >> 4, kw = w & 15;
            int so = row * RSA + kw * 2;
            *(uint32_t*)(AsHi + so) = f.aHi[i];
            *(uint32_t*)(AsLo + so) = f.aLo[i];
            int n = w & 127, kb = (w >> 7) * 2;
            int sb = n * RSA + kb;
            *(uint32_t*)(BsHi + sb) = f.bHi[i];
            *(uint32_t*)(BsLo + sb) = f.bLo[i];
        }
        __syncthreads();

        if (st + 1 < nStages)
            prefetchG1(f, A, Wpk, rowBase, M, K, lda, (st + 1) << 5, tid);

#pragma unroll
        for (int kkB = 0; kkB < 64; kkB += 32) {
            uint32_t bh[2][4], bl[2][4];
            ldsm4(bh[0], bBH + bOff[0] + kkB);
            ldsm4(bh[1], bBH + bOff[1] + kkB);
            ldsm4(bl[0], bBL + bOff[0] + kkB);
            ldsm4(bl[1], bBL + bOff[1] + kkB);
#pragma unroll
            for (int mt = 0; mt < 4; mt++) {
                uint32_t ah[4], al[4];
                ldsm4(ah, aBH + aOff[mt] + kkB);
                ldsm4(al, aBL + aOff[mt] + kkB);
#pragma unroll
                for (int nt = 0; nt < 4; nt++) {
                    const uint32_t* bhp = &bh[nt >> 1][(nt & 1) * 2];
                    const uint32_t* blp = &bl[nt >> 1][(nt & 1) * 2];
                    mma16816(acc[mt][nt], ah, bhp);
                    mma16816(acc[mt][nt], ah, blp);
                    mma16816(acc[mt][nt], al, bhp);
                }
            }
        }
        __syncthreads();
    }

#pragma unroll
    for (int mt = 0; mt < 4; mt++) {
        int r0 = rowBase + wm + mt * 16 + g;
        int r1 = r0 + 8;
        bool v0 = r0 < M, v1 = r1 < M;
#pragma unroll
        for (int nt = 0; nt < 4; nt++) {
            int cn = wn + nt * 8 + 2 * tig;
            float b0 = sBias[cn], b1 = sBias[cn + 1];
            float* c = acc[mt][nt];
            if (v0) {
                uint2 o = { packsplit(leaky(c[0] + b0)), packsplit(leaky(c[1] + b1)) };
                *(uint2*)(C0p + (size_t)r0 * D + cn) = o;
            }
            if (v1) {
                uint2 o = { packsplit(leaky(c[2] + b0)), packsplit(leaky(c[3] + b1)) };
                *(uint2*)(C0p + (size_t)r1 * D + cn) = o;
            }
        }
    }
}

// ---------------------------------------------------------------------------
// Weight prep: W_in k-major packed (pad 256); W_g, W_o1 n-major packed.
// ---------------------------------------------------------------------------
__global__ void k_prepW(const float* __restrict__ Win, const float* __restrict__ Wg,
                        const float* __restrict__ Wo1, int Kin)
{
    int i = blockIdx.x * blockDim.x + threadIdx.x;
    if (i < 256 * D) {
        int k = i >> 7, n = i & 127;
        float v = (k < Kin) ? Win[(size_t)k * D + n] : 0.f;
        g_WinPk[(size_t)k * D + n] = packsplit(v);
    } else if (i < 256 * D + D * D) {
        int j = i - 256 * D;
        int n = j >> 7, k = j & 127;
        g_WgT[(size_t)n * D + k] = packsplit(Wg[(size_t)k * D + n]);
    } else if (i < 256 * D + 2 * D * D) {
        int j = i - 256 * D - D * D;
        int n = j >> 7, k = j & 127;
        g_Wo1T[(size_t)n * D + k] = packsplit(Wo1[(size_t)k * D + n]);
    }
}

// ---------------------------------------------------------------------------
// CSR build (detect folded into zero; dinv folded into scan1)
// ---------------------------------------------------------------------------
__device__ __forceinline__ int edge_at(const void* ei, long long idx) {
    if (g_idx64) return (int)((const long long*)ei)[idx];
    return ((const int*)ei)[idx];
}

__global__ void k_zero(int* indeg, int n, const void* __restrict__ ei) {
    int i = blockIdx.x * blockDim.x + threadIdx.x;
    if (i < n) indeg[i] = 0;
    if (blockIdx.x == 0 && threadIdx.x == 0) {
        const long long* p = (const long long*)ei;
        int ok = 1;
        for (int j = 0; j < 16; j++) {
            long long v = p[j];
            if (v < 0 || v >= NMAX) ok = 0;
        }
        g_idx64 = ok;
    }
}
__global__ void k_count(const void* __restrict__ ei, int* indeg, int e) {
    int i = blockIdx.x * blockDim.x + threadIdx.x;
    if (i < e) atomicAdd(&indeg[edge_at(ei, (long long)e + i)], 1);
}

__global__ void k_scan1(const int* __restrict__ indeg, int* __restrict__ csr,
                        int* __restrict__ part, float* __restrict__ dinv, int n)
{
    __shared__ int sh[256];
    int t = threadIdx.x;
    int i = blockIdx.x * 256 + t;
    int v = (i < n) ? indeg[i] : 0;
    if (i < n) dinv[i] = rsqrtf(1.0f + (float)v);
    sh[t] = v;
    __syncthreads();
#pragma unroll
    for (int off = 1; off < 256; off <<= 1) {
        int x = (t >= off) ? sh[t - off] : 0;
        __syncthreads();
        sh[t] += x;
        __syncthreads();
    }
    if (i < n) csr[i] = sh[t] - v;
    if (t == 255) part[blockIdx.x] = sh[t];
}

__global__ void k_scan2(int* __restrict__ part, int nb) {
    __shared__ int sh[512];
    int t = threadIdx.x;
    int v = (t < nb) ? part[t] : 0;
    sh[t] = v;
    __syncthreads();
#pragma unroll
    for (int off = 1; off < 512; off <<= 1) {
        int x = (t >= off) ? sh[t - off] : 0;
        __syncthreads();
        sh[t] += x;
        __syncthreads();
    }
    if (t < nb) part[t] = sh[t] - v;
}

__global__ void k_scan3(int* __restrict__ csr, const int* __restrict__ part,
                        const int* __restrict__ indeg, int* __restrict__ cursor, int n)
{
    int i = blockIdx.x * blockDim.x + threadIdx.x;
    if (i >= n) return;
    int base = csr[i] + part[i >> 8];
    csr[i] = base;
    cursor[i] = 0;
    if (i == n - 1) csr[n] = base + indeg[i];
}

__global__ void k_fill(const void* __restrict__ ei, const float* __restrict__ dinv,
                       const int* __restrict__ csr, int* __restrict__ cursor,
                       int* __restrict__ srcS, float* __restrict__ normS, int E)
{
    int i = blockIdx.x * blockDim.x + threadIdx.x;
    if (i >= E) return;
    int s = edge_at(ei, i);
    int d = edge_at(ei, (long long)E + i);
    int p = csr[d] + atomicAdd(&cursor[d], 1);
    srcS[p] = s;
    normS[p] = dinv[s] * dinv[d];
}

// ---------------------------------------------------------------------------
// Gather: one warp per dst node; fp32 in, packed-split out.
// ---------------------------------------------------------------------------
__global__ __launch_bounds__(256) void k_gather(
    const float* __restrict__ t, const int* __restrict__ csr,
    const int* __restrict__ srcS, const float* __restrict__ normS,
    const float* __restrict__ dinv, const float* __restrict__ bias,
    uint32_t* __restrict__ aggp, int N)
{
    int warp = (blockIdx.x * blockDim.x + threadIdx.x) >> 5;
    int lane = threadIdx.x & 31;
    if (warp >= N) return;
    int beg = csr[warp], end = csr[warp + 1];
    float dv = dinv[warp];
    float dv2 = dv * dv;
    float4 b4 = *(const float4*)(bias + lane * 4);
    float4 a  = *(const float4*)(t + (size_t)warp * D + lane * 4);
    float4 acc;
    acc.x = a.x * dv2 + b4.x;
    acc.y = a.y * dv2 + b4.y;
    acc.z = a.z * dv2 + b4.z;
    acc.w = a.w * dv2 + b4.w;
    for (int e = beg; e < end; e++) {
        int s = srcS[e];
        float nm = normS[e];
        float4 v = *(const float4*)(t + (size_t)s * D + lane * 4);
        acc.x += nm * v.x;
        acc.y += nm * v.y;
        acc.z += nm * v.z;
        acc.w += nm * v.w;
    }
    uint4 o;
    o.x = packsplit(acc.x);
    o.y = packsplit(acc.y);
    o.z = packsplit(acc.z);
    o.w = packsplit(acc.w);
    *(uint4*)(aggp + (size_t)warp * D + lane * 4) = o;
}

// ---------------------------------------------------------------------------
// Host launcher
// ---------------------------------------------------------------------------
extern "C" void kernel_launch(void* const* d_in, const int* in_sizes, int n_in,
                              void* d_out, int out_size)
{
    const float* x    = (const float*)d_in[0];
    const void*  ei   = d_in[1];
    const float* W_in = (const float*)d_in[3];
    const float* b_in = (const float*)d_in[4];
    const float* W_g  = (const float*)d_in[5];
    const float* b_g  = (const float*)d_in[6];
    const float* W_o1 = (const float*)d_in[7];
    const float* b_o1 = (const float*)d_in[8];
    const float* W_o2 = (const float*)d_in[9];
    const float* b_o2 = (const float*)d_in[10];
    float*       out  = (float*)d_out;

    const int ND = 239;
    const int N  = in_sizes[0] / ND;
    const int E  = in_sizes[1] / 2;

    uint32_t *bufA, *bufC, *WinPk, *WgT, *Wo1T;
    float *bufB, *dinv, *normS;
    int *indeg, *csr, *cursor, *part, *srcS;
    cudaGetSymbolAddress((void**)&bufA,  g_bufA);
    cudaGetSymbolAddress((void**)&bufB,  g_bufB);
    cudaGetSymbolAddress((void**)&bufC,  g_bufC);
    cudaGetSymbolAddress((void**)&dinv,  g_dinv);
    cudaGetSymbolAddress((void**)&indeg, g_indeg);
    cudaGetSymbolAddress((void**)&csr,   g_csr);
    cudaGetSymbolAddress((void**)&cursor,g_cursor);
    cudaGetSymbolAddress((void**)&part,  g_part);
    cudaGetSymbolAddress((void**)&srcS,  g_srcS);
    cudaGetSymbolAddress((void**)&normS, g_normS);
    cudaGetSymbolAddress((void**)&WinPk, g_WinPk);
    cudaGetSymbolAddress((void**)&WgT,   g_WgT);
    cudaGetSymbolAddress((void**)&Wo1T,  g_Wo1T);

    cudaFuncSetAttribute(k_gemm_fast, cudaFuncAttributeMaxDynamicSharedMemorySize, SMEM_FAST);

    const int TB = 256;
    const int nBlk = (N + 255) / 256;

    k_zero<<<nBlk, TB>>>(indeg, N, ei);
    k_count<<<(E + TB - 1) / TB, TB>>>(ei, indeg, E);
    k_scan1<<<nBlk, TB>>>(indeg, csr, part, dinv, N);
    k_scan2<<<1, 512>>>(part, nBlk);
    k_scan3<<<nBlk, TB>>>(csr, part, indeg, cursor, N);
    k_fill<<<(E + TB - 1) / TB, TB>>>(ei, dinv, csr, cursor, srcS, normS, E);
    k_prepW<<<(256 * D + 2 * D * D + TB - 1) / TB, TB>>>(W_in, W_g, W_o1, ND);

    const int grid = (N + 127) / 128;
    const int gGrid = ((size_t)N * 32 + TB - 1) / TB;
    // G1: h0 = pk(leaky(x @ W_in + b_in)) -> A
    k_gemm_g1<<<grid, TB>>>(x, WinPk, b_in, bufA, N, ND, ND);
    // G2: t1 = h0 @ W_g -> B (fp32)
    k_gemm_fast<<<grid, TB, SMEM_FAST>>>(bufA, WgT, nullptr, bufB,
                                         nullptr, nullptr, nullptr, N, 0);
    k_gather<<<gGrid, TB>>>(bufB, csr, srcS, normS, dinv, b_g, bufC, N);
    // G3: t2 = h1 @ W_g -> B (fp32)
    k_gemm_fast<<<grid, TB, SMEM_FAST>>>(bufC, WgT, nullptr, bufB,
                                         nullptr, nullptr, nullptr, N, 0);
    k_gather<<<gGrid, TB>>>(bufB, csr, srcS, normS, dinv, b_g, bufA, N);
    // G4: out = leaky(h2 @ W_o1 + b_o1) @ W_o2 + b_o2  (fully fused)
    k_gemm_fast<<<grid, TB, SMEM_FAST>>>(bufA, Wo1T, b_o1, nullptr,
                                         W_o2, b_o2, out, N, 3);
}

// round 14
// speedup vs baseline: 1.1209x; 1.0388x over previous
#include <cuda_runtime.h>
#include <cuda_bf16.h>
#include <cstdint>
#include <math.h>

#define NMAX 100000
#define EMAX 640000
#define D    128

// Scratch. bufA/C packed-split activations (uint32), bufB fp32 t.
__device__ uint32_t g_bufA[(size_t)NMAX * D];
__device__ float    g_bufB[(size_t)NMAX * D];
__device__ uint32_t g_bufC[(size_t)NMAX * D];
__device__ float    g_dinv[NMAX];
__device__ int      g_indeg[NMAX];
__device__ int      g_csr[NMAX + 1];
__device__ int      g_cursor[NMAX];
__device__ int      g_part[512];
__device__ int      g_srcS[EMAX];
__device__ float    g_normS[EMAX];
__device__ int      g_idx64;
// Pre-split weights (packed hi|lo<<16).
__device__ uint32_t g_WinPk[256 * D];   // k-major [k][n], K padded 256 (G1)
__device__ uint32_t g_WgT [D * D];      // n-major [n][k] (G2/G3)
__device__ uint32_t g_Wo1T[D * D];      // n-major [n][k] (G4)

__device__ __forceinline__ float leaky(float v) { return v >= 0.f ? v : 0.01f * v; }

__device__ __forceinline__ uint32_t packsplit(float v) {
    __nv_bfloat16 h = __float2bfloat16(v);
    __nv_bfloat16 l = __float2bfloat16(v - __bfloat162float(h));
    return (uint32_t)__bfloat16_as_ushort(h) | ((uint32_t)__bfloat16_as_ushort(l) << 16);
}
__device__ __forceinline__ uint32_t pack_hi(float a0, float a1) {
    __nv_bfloat16 h0 = __float2bfloat16(a0), h1 = __float2bfloat16(a1);
    return (uint32_t)__bfloat16_as_ushort(h0) | ((uint32_t)__bfloat16_as_ushort(h1) << 16);
}
__device__ __forceinline__ uint32_t pack_lo(float a0, float a1) {
    __nv_bfloat16 h0 = __float2bfloat16(a0), h1 = __float2bfloat16(a1);
    __nv_bfloat16 l0 = __float2bfloat16(a0 - __bfloat162float(h0));
    __nv_bfloat16 l1 = __float2bfloat16(a1 - __bfloat162float(h1));
    return (uint32_t)__bfloat16_as_ushort(l0) | ((uint32_t)__bfloat16_as_ushort(l1) << 16);
}

__device__ __forceinline__ void mma16816(float* c, const uint32_t* a, const uint32_t* b) {
    asm volatile(
        "mma.sync.aligned.m16n8k16.row.col.f32.bf16.bf16.f32 "
        "{%0,%1,%2,%3}, {%4,%5,%6,%7}, {%8,%9}, {%0,%1,%2,%3};"
        : "+f"(c[0]), "+f"(c[1]), "+f"(c[2]), "+f"(c[3])
        : "r"(a[0]), "r"(a[1]), "r"(a[2]), "r"(a[3]), "r"(b[0]), "r"(b[1]));
}
__device__ __forceinline__ void ldsm4(uint32_t* r, uint32_t addr) {
    asm volatile("ldmatrix.sync.aligned.m8n8.x4.shared.b16 {%0,%1,%2,%3}, [%4];"
                 : "=r"(r[0]), "=r"(r[1]), "=r"(r[2]), "=r"(r[3]) : "r"(addr));
}

#define RSA 40   // A smem row stride (halves)
#define RSB 136  // B resident row stride (halves)

// Dynamic smem layout for fast kernel (bytes)
#define OFF_BH   0
#define OFF_BL   (OFF_BH + 128 * RSB * 2)
#define OFF_AH   (OFF_BL + 128 * RSB * 2)
#define OFF_AL   (OFF_AH + 128 * RSA * 2)
#define OFF_BIAS (OFF_AL + 128 * RSA * 2)
#define OFF_W2   (OFF_BIAS + 512)
#define OFF_PROJ (OFF_W2 + 1024)
#define SMEM_FAST (OFF_PROJ + 1024)

// ---------------------------------------------------------------------------
// FAST GEMM (K=128): A packed-split uint32, W resident n-major packed.
// mode 0: C0f = acc (fp32).  mode 3: fused leaky+bias+projection -> outp.
// ---------------------------------------------------------------------------
__global__ __launch_bounds__(256, 2) void k_gemm_fast(
    const uint32_t* __restrict__ A, const uint32_t* __restrict__ Wt,
    const float* __restrict__ bias,
    float* __restrict__ C0f,
    const float* __restrict__ w2, const float* __restrict__ b2,
    float* __restrict__ outp,
    int M, int mode)
{
    extern __shared__ __align__(16) char sm[];
    __nv_bfloat16* BsHi = (__nv_bfloat16*)(sm + OFF_BH);
    __nv_bfloat16* BsLo = (__nv_bfloat16*)(sm + OFF_BL);
    __nv_bfloat16* AsHi = (__nv_bfloat16*)(sm + OFF_AH);
    __nv_bfloat16* AsLo = (__nv_bfloat16*)(sm + OFF_AL);
    float* sBias = (float*)(sm + OFF_BIAS);
    float* sW2   = (float*)(sm + OFF_W2);
    float* sProj = (float*)(sm + OFF_PROJ);

    const int tid  = threadIdx.x;
    const int wid  = tid >> 5;
    const int lane = tid & 31;
    const int g    = lane >> 2;
    const int tig  = lane & 3;
    const int wm   = (wid >> 2) * 64;
    const int wn   = (wid & 3) * 32;
    const int rowBase = blockIdx.x * 128;

    if (mode == 3) {
        if (tid < 128) sBias[tid] = bias[tid];
        sW2[tid] = w2[tid];
        if (tid < 128) { sProj[tid * 2] = 0.f; sProj[tid * 2 + 1] = 0.f; }
    }

    // ---- load resident B (whole 128x128 weight, n-major packed) ----
    {
        int n = tid >> 1;
        int kb = (tid & 1) * 64;
        const uint32_t* wrow = Wt + (size_t)n * 128 + kb;
#pragma unroll
        for (int i = 0; i < 32; i++) {
            uint2 q = *(const uint2*)(wrow + 2 * i);
            *(uint32_t*)(BsHi + n * RSB + kb + 2 * i) = __byte_perm(q.x, q.y, 0x5410);
            *(uint32_t*)(BsLo + n * RSB + kb + 2 * i) = __byte_perm(q.x, q.y, 0x7632);
        }
    }

    const uint32_t aBH = (uint32_t)__cvta_generic_to_shared(AsHi);
    const uint32_t aBL = (uint32_t)__cvta_generic_to_shared(AsLo);
    const uint32_t bBH = (uint32_t)__cvta_generic_to_shared(BsHi);
    const uint32_t bBL = (uint32_t)__cvta_generic_to_shared(BsLo);
    const int aRow  = wm + (lane & 15);
    const int aColH = (lane >> 4) * 8;
    uint32_t aOff[4];
#pragma unroll
    for (int mt = 0; mt < 4; mt++)
        aOff[mt] = (uint32_t)(((aRow + mt * 16) * RSA + aColH) * 2);
    const int bQ  = lane >> 3, bL7 = lane & 7;
    const int bNo = ((bQ >> 1) & 1) * 8 + bL7;
    const int bKo = (bQ & 1) * 8;
    uint32_t bOff[2];
#pragma unroll
    for (int p = 0; p < 2; p++)
        bOff[p] = (uint32_t)(((wn + p * 16 + bNo) * RSB + bKo) * 2);

    float acc[4][4][4];
#pragma unroll
    for (int mt = 0; mt < 4; mt++)
#pragma unroll
        for (int nt = 0; nt < 4; nt++)
#pragma unroll
            for (int j = 0; j < 4; j++) acc[mt][nt][j] = 0.f;

    uint32_t aHi[8], aLo[8];
#pragma unroll
    for (int i = 0; i < 8; i++) {
        int w = tid + i * 256;
        int row = w >> 4, kw = w & 15;
        int grow = rowBase + row;
        uint2 p = make_uint2(0u, 0u);
        if (grow < M) p = *(const uint2*)(A + (size_t)grow * 128 + kw * 2);
        aHi[i] = __byte_perm(p.x, p.y, 0x5410);
        aLo[i] = __byte_perm(p.x, p.y, 0x7632);
    }

    for (int st = 0; st < 4; st++) {
#pragma unroll
        for (int i = 0; i < 8; i++) {
            int w = tid + i * 256;
            int row = w >> 4, kw = w & 15;
            int so = row * RSA + kw * 2;
            *(uint32_t*)(AsHi + so) = aHi[i];
            *(uint32_t*)(AsLo + so) = aLo[i];
        }
        __syncthreads();

        if (st < 3) {
            int k0 = (st + 1) << 5;
#pragma unroll
            for (int i = 0; i < 8; i++) {
                int w = tid + i * 256;
                int row = w >> 4, kw = w & 15;
                int grow = rowBase + row;
                uint2 p = make_uint2(0u, 0u);
                if (grow < M) p = *(const uint2*)(A + (size_t)grow * 128 + k0 + kw * 2);
                aHi[i] = __byte_perm(p.x, p.y, 0x5410);
                aLo[i] = __byte_perm(p.x, p.y, 0x7632);
            }
        }

        const int stB = st * 64;
#pragma unroll
        for (int kkB = 0; kkB < 64; kkB += 32) {
            uint32_t bh[2][4], bl[2][4];
            ldsm4(bh[0], bBH + bOff[0] + stB + kkB);
            ldsm4(bh[1], bBH + bOff[1] + stB + kkB);
            ldsm4(bl[0], bBL + bOff[0] + stB + kkB);
            ldsm4(bl[1], bBL + bOff[1] + stB + kkB);
#pragma unroll
            for (int mt = 0; mt < 4; mt++) {
                uint32_t ah[4], al[4];
                ldsm4(ah, aBH + aOff[mt] + kkB);
                ldsm4(al, aBL + aOff[mt] + kkB);
#pragma unroll
                for (int nt = 0; nt < 4; nt++) {
                    const uint32_t* bhp = &bh[nt >> 1][(nt & 1) * 2];
                    const uint32_t* blp = &bl[nt >> 1][(nt & 1) * 2];
                    mma16816(acc[mt][nt], ah, bhp);
                    mma16816(acc[mt][nt], ah, blp);
                    mma16816(acc[mt][nt], al, bhp);
                }
            }
        }
        __syncthreads();
    }

    if (mode == 3) {
#pragma unroll
        for (int mt = 0; mt < 4; mt++) {
            float p00 = 0.f, p01 = 0.f, p10 = 0.f, p11 = 0.f;
#pragma unroll
            for (int nt = 0; nt < 4; nt++) {
                int cn = wn + nt * 8 + 2 * tig;
                float b0 = sBias[cn], b1 = sBias[cn + 1];
                float w00 = sW2[cn * 2], w01 = sW2[cn * 2 + 1];
                float w10 = sW2[cn * 2 + 2], w11 = sW2[cn * 2 + 3];
                float* c = acc[mt][nt];
                float h0 = leaky(c[0] + b0), h1 = leaky(c[1] + b1);
                p00 += h0 * w00 + h1 * w10;
                p01 += h0 * w01 + h1 * w11;
                float h2 = leaky(c[2] + b0), h3 = leaky(c[3] + b1);
                p10 += h2 * w00 + h3 * w10;
                p11 += h2 * w01 + h3 * w11;
            }
#pragma unroll
            for (int off = 1; off < 4; off <<= 1) {
                p00 += __shfl_xor_sync(0xFFFFFFFFu, p00, off);
                p01 += __shfl_xor_sync(0xFFFFFFFFu, p01, off);
                p10 += __shfl_xor_sync(0xFFFFFFFFu, p10, off);
                p11 += __shfl_xor_sync(0xFFFFFFFFu, p11, off);
            }
            if (tig == 0) {
                int lr = wm + mt * 16 + g;
                atomicAdd(&sProj[lr * 2], p00);
                atomicAdd(&sProj[lr * 2 + 1], p01);
                atomicAdd(&sProj[(lr + 8) * 2], p10);
                atomicAdd(&sProj[(lr + 8) * 2 + 1], p11);
            }
        }
        __syncthreads();
        {
            int lr = tid >> 1, c = tid & 1;
            int grow = rowBase + lr;
            if (grow < M) outp[(size_t)grow * 2 + c] = sProj[lr * 2 + c] + b2[c];
        }
        return;
    }

#pragma unroll
    for (int mt = 0; mt < 4; mt++) {
        int r0 = rowBase + wm + mt * 16 + g;
        int r1 = r0 + 8;
        bool v0 = r0 < M, v1 = r1 < M;
#pragma unroll
        for (int nt = 0; nt < 4; nt++) {
            int cn = wn + nt * 8 + 2 * tig;
            float* c = acc[mt][nt];
            if (v0) { float2 o = { c[0], c[1] }; *(float2*)(C0f + (size_t)r0 * D + cn) = o; }
            if (v1) { float2 o = { c[2], c[3] }; *(float2*)(C0f + (size_t)r1 * D + cn) = o; }
        }
    }
}

// ---------------------------------------------------------------------------
// G1 GEMM (K=239, fp32 A, k-major packed W, per-stage staging).
// ---------------------------------------------------------------------------
struct FragG1 { uint32_t aHi[8], aLo[8], bHi[8], bLo[8]; };

__device__ __forceinline__ void prefetchG1(
    FragG1& f, const float* __restrict__ A, const uint32_t* __restrict__ Wpk,
    int rowBase, int M, int K, int lda, int k0, int tid)
{
#pragma unroll
    for (int i = 0; i < 8; i++) {
        int w = tid + i * 256;
        int row = w >> 4, kw = w & 15;
        int grow = rowBase + row, gk = k0 + kw * 2;
        float a0 = 0.f, a1 = 0.f;
        if (grow < M) {
            const float* ap = A + (size_t)grow * lda;
            if (gk < K)     a0 = ap[gk];
            if (gk + 1 < K) a1 = ap[gk + 1];
        }
        f.aHi[i] = pack_hi(a0, a1);
        f.aLo[i] = pack_lo(a0, a1);
    }
#pragma unroll
    for (int i = 0; i < 8; i++) {
        int w = tid + i * 256;
        int n = w & 127, kw = w >> 7;
        int gk = k0 + kw * 2;
        uint32_t q0 = Wpk[(size_t)gk * D + n];
        uint32_t q1 = Wpk[(size_t)(gk + 1) * D + n];
        f.bHi[i] = __byte_perm(q0, q1, 0x5410);
        f.bLo[i] = __byte_perm(q0, q1, 0x7632);
    }
}

__global__ __launch_bounds__(256, 2) void k_gemm_g1(
    const float* __restrict__ A, const uint32_t* __restrict__ Wpk,
    const float* __restrict__ bias, uint32_t* __restrict__ C0p,
    int M, int K, int lda)
{
    __shared__ float sBias[128];
    __shared__ __align__(16) __nv_bfloat16 AsHi[128 * RSA];
    __shared__ __align__(16) __nv_bfloat16 AsLo[128 * RSA];
    __shared__ __align__(16) __nv_bfloat16 BsHi[128 * RSA];
    __shared__ __align__(16) __nv_bfloat16 BsLo[128 * RSA];

    const int tid  = threadIdx.x;
    const int wid  = tid >> 5;
    const int lane = tid & 31;
    const int g    = lane >> 2;
    const int tig  = lane & 3;
    const int wm   = (wid >> 2) * 64;
    const int wn   = (wid & 3) * 32;
    const int rowBase = blockIdx.x * 128;

    if (tid < 128) sBias[tid] = bias[tid];

    const uint32_t aBH = (uint32_t)__cvta_generic_to_shared(AsHi);
    const uint32_t aBL = (uint32_t)__cvta_generic_to_shared(AsLo);
    const uint32_t bBH = (uint32_t)__cvta_generic_to_shared(BsHi);
    const uint32_t bBL = (uint32_t)__cvta_generic_to_shared(BsLo);
    const int aRow  = wm + (lane & 15);
    const int aColH = (lane >> 4) * 8;
    uint32_t aOff[4];
#pragma unroll
    for (int mt = 0; mt < 4; mt++)
        aOff[mt] = (uint32_t)(((aRow + mt * 16) * RSA + aColH) * 2);
    const int bQ  = lane >> 3, bL7 = lane & 7;
    const int bNo = ((bQ >> 1) & 1) * 8 + bL7;
    const int bKo = (bQ & 1) * 8;
    uint32_t bOff[2];
#pragma unroll
    for (int p = 0; p < 2; p++)
        bOff[p] = (uint32_t)(((wn + p * 16 + bNo) * RSA + bKo) * 2);

    float acc[4][4][4];
#pragma unroll
    for (int mt = 0; mt < 4; mt++)
#pragma unroll
        for (int nt = 0; nt < 4; nt++)
#pragma unroll
            for (int j = 0; j < 4; j++) acc[mt][nt][j] = 0.f;

    const int nStages = (K + 31) >> 5;
    FragG1 f;
    prefetchG1(f, A, Wpk, rowBase, M, K, lda, 0, tid);

    for (int st = 0; st < nStages; st++) {
#pragma unroll
        for (int i = 0; i < 8; i++) {
            int w = tid + i * 256;
            int row = w >> 4, kw = w & 15;
            int so = row * RSA + kw * 2;
            *(uint32_t*)(AsHi + so) = f.aHi[i];
            *(uint32_t*)(AsLo + so) = f.aLo[i];
            int n = w & 127, kb = (w >> 7) * 2;
            int sb = n * RSA + kb;
            *(uint32_t*)(BsHi + sb) = f.bHi[i];
            *(uint32_t*)(BsLo + sb) = f.bLo[i];
        }
        __syncthreads();

        if (st + 1 < nStages)
            prefetchG1(f, A, Wpk, rowBase, M, K, lda, (st + 1) << 5, tid);

#pragma unroll
        for (int kkB = 0; kkB < 64; kkB += 32) {
            uint32_t bh[2][4], bl[2][4];
            ldsm4(bh[0], bBH + bOff[0] + kkB);
            ldsm4(bh[1], bBH + bOff[1] + kkB);
            ldsm4(bl[0], bBL + bOff[0] + kkB);
            ldsm4(bl[1], bBL + bOff[1] + kkB);
#pragma unroll
            for (int mt = 0; mt < 4; mt++) {
                uint32_t ah[4], al[4];
                ldsm4(ah, aBH + aOff[mt] + kkB);
                ldsm4(al, aBL + aOff[mt] + kkB);
#pragma unroll
                for (int nt = 0; nt < 4; nt++) {
                    const uint32_t* bhp = &bh[nt >> 1][(nt & 1) * 2];
                    const uint32_t* blp = &bl[nt >> 1][(nt & 1) * 2];
                    mma16816(acc[mt][nt], ah, bhp);
                    mma16816(acc[mt][nt], ah, blp);
                    mma16816(acc[mt][nt], al, bhp);
                }
            }
        }
        __syncthreads();
    }

#pragma unroll
    for (int mt = 0; mt < 4; mt++) {
        int r0 = rowBase + wm + mt * 16 + g;
        int r1 = r0 + 8;
        bool v0 = r0 < M, v1 = r1 < M;
#pragma unroll
        for (int nt = 0; nt < 4; nt++) {
            int cn = wn + nt * 8 + 2 * tig;
            float b0 = sBias[cn], b1 = sBias[cn + 1];
            float* c = acc[mt][nt];
            if (v0) {
                uint2 o = { packsplit(leaky(c[0] + b0)), packsplit(leaky(c[1] + b1)) };
                *(uint2*)(C0p + (size_t)r0 * D + cn) = o;
            }
            if (v1) {
                uint2 o = { packsplit(leaky(c[2] + b0)), packsplit(leaky(c[3] + b1)) };
                *(uint2*)(C0p + (size_t)r1 * D + cn) = o;
            }
        }
    }
}

// ---------------------------------------------------------------------------
// Weight prep
// ---------------------------------------------------------------------------
__global__ void k_prepW(const float* __restrict__ Win, const float* __restrict__ Wg,
                        const float* __restrict__ Wo1, int Kin)
{
    int i = blockIdx.x * blockDim.x + threadIdx.x;
    if (i < 256 * D) {
        int k = i >> 7, n = i & 127;
        float v = (k < Kin) ? Win[(size_t)k * D + n] : 0.f;
        g_WinPk[(size_t)k * D + n] = packsplit(v);
    } else if (i < 256 * D + D * D) {
        int j = i - 256 * D;
        int n = j >> 7, k = j & 127;
        g_WgT[(size_t)n * D + k] = packsplit(Wg[(size_t)k * D + n]);
    } else if (i < 256 * D + 2 * D * D) {
        int j = i - 256 * D - D * D;
        int n = j >> 7, k = j & 127;
        g_Wo1T[(size_t)n * D + k] = packsplit(Wo1[(size_t)k * D + n]);
    }
}

// ---------------------------------------------------------------------------
// CSR build (runs on side stream, overlapped with G1/G2)
// ---------------------------------------------------------------------------
__global__ void k_detect(const void* __restrict__ ei) {
    const long long* p = (const long long*)ei;
    int ok = 1;
    for (int i = 0; i < 16; i++) {
        long long v = p[i];
        if (v < 0 || v >= NMAX) ok = 0;
    }
    g_idx64 = ok;
}
__device__ __forceinline__ int edge_at(const void* ei, long long idx) {
    if (g_idx64) return (int)((const long long*)ei)[idx];
    return ((const int*)ei)[idx];
}

__global__ void k_count(const void* __restrict__ ei, int* indeg, int e) {
    int i = blockIdx.x * blockDim.x + threadIdx.x;
    if (i < e) atomicAdd(&indeg[edge_at(ei, (long long)e + i)], 1);
}

__global__ void k_scan1(const int* __restrict__ indeg, int* __restrict__ csr,
                        int* __restrict__ part, float* __restrict__ dinv, int n)
{
    __shared__ int sh[256];
    int t = threadIdx.x;
    int i = blockIdx.x * 256 + t;
    int v = (i < n) ? indeg[i] : 0;
    if (i < n) dinv[i] = rsqrtf(1.0f + (float)v);
    sh[t] = v;
    __syncthreads();
#pragma unroll
    for (int off = 1; off < 256; off <<= 1) {
        int x = (t >= off) ? sh[t - off] : 0;
        __syncthreads();
        sh[t] += x;
        __syncthreads();
    }
    if (i < n) csr[i] = sh[t] - v;
    if (t == 255) part[blockIdx.x] = sh[t];
}

__global__ void k_scan2(int* __restrict__ part, int nb) {
    __shared__ int sh[512];
    int t = threadIdx.x;
    int v = (t < nb) ? part[t] : 0;
    sh[t] = v;
    __syncthreads();
#pragma unroll
    for (int off = 1; off < 512; off <<= 1) {
        int x = (t >= off) ? sh[t - off] : 0;
        __syncthreads();
        sh[t] += x;
        __syncthreads();
    }
    if (t < nb) part[t] = sh[t] - v;
}

__global__ void k_scan3(int* __restrict__ csr, const int* __restrict__ part,
                        const int* __restrict__ indeg, int* __restrict__ cursor, int n)
{
    int i = blockIdx.x * blockDim.x + threadIdx.x;
    if (i >= n) return;
    int base = csr[i] + part[i >> 8];
    csr[i] = base;
    cursor[i] = 0;
    if (i == n - 1) csr[n] = base + indeg[i];
}

__global__ void k_fill(const void* __restrict__ ei, const float* __restrict__ dinv,
                       const int* __restrict__ csr, int* __restrict__ cursor,
                       int* __restrict__ srcS, float* __restrict__ normS, int E)
{
    int i = blockIdx.x * blockDim.x + threadIdx.x;
    if (i >= E) return;
    int s = edge_at(ei, i);
    int d = edge_at(ei, (long long)E + i);
    int p = csr[d] + atomicAdd(&cursor[d], 1);
    srcS[p] = s;
    normS[p] = dinv[s] * dinv[d];
}

// ---------------------------------------------------------------------------
// Gather: one warp per dst node; fp32 in, packed-split out.
// ---------------------------------------------------------------------------
__global__ __launch_bounds__(256) void k_gather(
    const float* __restrict__ t, const int* __restrict__ csr,
    const int* __restrict__ srcS, const float* __restrict__ normS,
    const float* __restrict__ dinv, const float* __restrict__ bias,
    uint32_t* __restrict__ aggp, int N)
{
    int warp = (blockIdx.x * blockDim.x + threadIdx.x) >> 5;
    int lane = threadIdx.x & 31;
    if (warp >= N) return;
    int beg = csr[warp], end = csr[warp + 1];
    float dv = dinv[warp];
    float dv2 = dv * dv;
    float4 b4 = *(const float4*)(bias + lane * 4);
    float4 a  = *(const float4*)(t + (size_t)warp * D + lane * 4);
    float4 acc;
    acc.x = a.x * dv2 + b4.x;
    acc.y = a.y * dv2 + b4.y;
    acc.z = a.z * dv2 + b4.z;
    acc.w = a.w * dv2 + b4.w;
    for (int e = beg; e < end; e++) {
        int s = srcS[e];
        float nm = normS[e];
        float4 v = *(const float4*)(t + (size_t)s * D + lane * 4);
        acc.x += nm * v.x;
        acc.y += nm * v.y;
        acc.z += nm * v.z;
        acc.w += nm * v.w;
    }
    uint4 o;
    o.x = packsplit(acc.x);
    o.y = packsplit(acc.y);
    o.z = packsplit(acc.z);
    o.w = packsplit(acc.w);
    *(uint4*)(aggp + (size_t)warp * D + lane * 4) = o;
}

// ---------------------------------------------------------------------------
// Host launcher — two-stream fork/join (graph-capture safe)
// ---------------------------------------------------------------------------
extern "C" void kernel_launch(void* const* d_in, const int* in_sizes, int n_in,
                              void* d_out, int out_size)
{
    const float* x    = (const float*)d_in[0];
    const void*  ei   = d_in[1];
    const float* W_in = (const float*)d_in[3];
    const float* b_in = (const float*)d_in[4];
    const float* W_g  = (const float*)d_in[5];
    const float* b_g  = (const float*)d_in[6];
    const float* W_o1 = (const float*)d_in[7];
    const float* b_o1 = (const float*)d_in[8];
    const float* W_o2 = (const float*)d_in[9];
    const float* b_o2 = (const float*)d_in[10];
    float*       out  = (float*)d_out;

    const int ND = 239;
    const int N  = in_sizes[0] / ND;
    const int E  = in_sizes[1] / 2;

    uint32_t *bufA, *bufC, *WinPk, *WgT, *Wo1T;
    float *bufB, *dinv, *normS;
    int *indeg, *csr, *cursor, *part, *srcS;
    cudaGetSymbolAddress((void**)&bufA,  g_bufA);
    cudaGetSymbolAddress((void**)&bufB,  g_bufB);
    cudaGetSymbolAddress((void**)&bufC,  g_bufC);
    cudaGetSymbolAddress((void**)&dinv,  g_dinv);
    cudaGetSymbolAddress((void**)&indeg, g_indeg);
    cudaGetSymbolAddress((void**)&csr,   g_csr);
    cudaGetSymbolAddress((void**)&cursor,g_cursor);
    cudaGetSymbolAddress((void**)&part,  g_part);
    cudaGetSymbolAddress((void**)&srcS,  g_srcS);
    cudaGetSymbolAddress((void**)&normS, g_normS);
    cudaGetSymbolAddress((void**)&WinPk, g_WinPk);
    cudaGetSymbolAddress((void**)&WgT,   g_WgT);
    cudaGetSymbolAddress((void**)&Wo1T,  g_Wo1T);

    static cudaStream_t s2 = nullptr;
    static cudaEvent_t evF = nullptr, evJ = nullptr;
    static bool inited = false;
    if (!inited) {
        cudaStreamCreateWithFlags(&s2, cudaStreamNonBlocking);
        cudaEventCreateWithFlags(&evF, cudaEventDisableTiming);
        cudaEventCreateWithFlags(&evJ, cudaEventDisableTiming);
        cudaFuncSetAttribute(k_gemm_fast, cudaFuncAttributeMaxDynamicSharedMemorySize, SMEM_FAST);
        inited = true;
    }

    const int TB = 256;
    const int nBlk = (N + 255) / 256;
    const int grid = (N + 127) / 128;
    const int gGrid = (int)(((size_t)N * 32 + TB - 1) / TB);

    // ---- fork: CSR chain on s2 ----
    cudaEventRecord(evF, 0);
    cudaStreamWaitEvent(s2, evF, 0);
    cudaMemsetAsync(indeg, 0, (size_t)N * sizeof(int), s2);
    k_detect<<<1, 1, 0, s2>>>(ei);
    k_count<<<(E + TB - 1) / TB, TB, 0, s2>>>(ei, indeg, E);
    k_scan1<<<nBlk, TB, 0, s2>>>(indeg, csr, part, dinv, N);
    k_scan2<<<1, 512, 0, s2>>>(part, nBlk);
    k_scan3<<<nBlk, TB, 0, s2>>>(csr, part, indeg, cursor, N);
    k_fill<<<(E + TB - 1) / TB, TB, 0, s2>>>(ei, dinv, csr, cursor, srcS, normS, E);
    cudaEventRecord(evJ, s2);

    // ---- main stream: weight prep + GEMM chain ----
    k_prepW<<<(256 * D + 2 * D * D + TB - 1) / TB, TB>>>(W_in, W_g, W_o1, ND);
    // G1: h0 = pk(leaky(x @ W_in + b_in)) -> A
    k_gemm_g1<<<grid, TB>>>(x, WinPk, b_in, bufA, N, ND, ND);
    // G2: t1 = h0 @ W_g -> B (fp32)
    k_gemm_fast<<<grid, TB, SMEM_FAST>>>(bufA, WgT, nullptr, bufB,
                                         nullptr, nullptr, nullptr, N, 0);
    // ---- join: CSR must be ready for gather ----
    cudaStreamWaitEvent(0, evJ, 0);
    k_gather<<<gGrid, TB>>>(bufB, csr, srcS, normS, dinv, b_g, bufC, N);
    // G3: t2 = h1 @ W_g -> B (fp32)
    k_gemm_fast<<<grid, TB, SMEM_FAST>>>(bufC, WgT, nullptr, bufB,
                                         nullptr, nullptr, nullptr, N, 0);
    k_gather<<<gGrid, TB>>>(bufB, csr, srcS, normS, dinv, b_g, bufA, N);
    // G4: out = leaky(h2 @ W_o1 + b_o1) @ W_o2 + b_o2  (fully fused)
    k_gemm_fast<<<grid, TB, SMEM_FAST>>>(bufA, Wo1T, b_o1, nullptr,
                                         W_o2, b_o2, out, N, 3);
}